// round 1
// baseline (speedup 1.0000x reference)
#include <cuda_runtime.h>
#include <cstdint>

#define NQ      8
#define NLAYERS 4
#define DIN     1024
#define DOUT    1024

// Precomputed combined RZ(phi)*RX(theta) 2x2 complex coefficients for the 32
// layer gates: [l*8+i][8] = {u00r,u00i, u01r,u01i, u10r,u10i, u11r,u11i}
__device__ float g_ucoef[NLAYERS * NQ * 8];

__global__ void prep_kernel(const float* __restrict__ qw) {
    int t = threadIdx.x;
    if (t < NLAYERS * NQ) {
        int l = t >> 3, i = t & 7;
        float th = qw[l * 16 + i];        // weights[l][0][i] (RX)
        float ph = qw[l * 16 + 8 + i];    // weights[l][1][i] (RZ)
        float s, c, sp, cp;
        sincosf(0.5f * th, &s, &c);
        sincosf(0.5f * ph, &sp, &cp);
        float* u = &g_ucoef[t * 8];
        // U = diag(e^{-i ph/2}, e^{i ph/2}) * [[c, -i s],[-i s, c]]
        u[0] =  c * cp;  u[1] = -c * sp;   // u00
        u[2] = -s * sp;  u[3] = -s * cp;   // u01
        u[4] =  s * sp;  u[5] = -s * cp;   // u10
        u[6] =  c * cp;  u[7] =  c * sp;   // u11
    }
}

// One warp simulates one batch row. Amplitude index k = lane*8 + r.
// Wire i uses bit (7-i) of k:  wires 0..4 -> lane bits 4..0, wires 5..7 -> r bits 2..0.
__global__ __launch_bounds__(256, 2)
void qasa_kernel(const float* __restrict__ x,
                 const float* __restrict__ Win,
                 const float* __restrict__ bin,
                 const float* __restrict__ Wout,
                 const float* __restrict__ bout,
                 float* __restrict__ out)
{
    const int lane = threadIdx.x & 31;
    const int warp = threadIdx.x >> 5;
    const int row  = blockIdx.x * 8 + warp;

    // ---------------- 1) angles = x[row] @ Win^T + bin ----------------
    float acc[NQ];
#pragma unroll
    for (int q = 0; q < NQ; q++) acc[q] = 0.f;

    const float4* x4 = reinterpret_cast<const float4*>(x + (size_t)row * DIN);
    const float4* w4 = reinterpret_cast<const float4*>(Win);
#pragma unroll
    for (int j = 0; j < 8; j++) {
        float4 xv = __ldcs(&x4[lane + 32 * j]);   // streaming: don't pollute L1
#pragma unroll
        for (int q = 0; q < NQ; q++) {
            float4 wv = __ldg(&w4[q * 256 + lane + 32 * j]);
            acc[q] += xv.x * wv.x + xv.y * wv.y + xv.z * wv.z + xv.w * wv.w;
        }
    }
#pragma unroll
    for (int off = 16; off; off >>= 1)
#pragma unroll
        for (int q = 0; q < NQ; q++)
            acc[q] += __shfl_xor_sync(0xffffffffu, acc[q], off);

    // C = cos(theta/2), S = sin(theta/2) for each wire (all lanes have all angles)
    float C[NQ], S[NQ];
#pragma unroll
    for (int q = 0; q < NQ; q++) {
        float h = 0.5f * (acc[q] + __ldg(&bin[q]));
        __sincosf(h, &S[q], &C[q]);
    }

    // ---------------- 2) initial product state -----------------------
    // After RX(th)RZ(th): qubit vector q0=(C^2, -S*C), q1=(S^2, -S*C)
    float ar[8], ai[8];
    {
        float prr = 1.f, pri = 0.f;
#pragma unroll
        for (int w = 0; w < 5; w++) {
            int b = (lane >> (4 - w)) & 1;
            float qr = b ? S[w] * S[w] : C[w] * C[w];
            float qi = -S[w] * C[w];
            float nr = prr * qr - pri * qi;
            pri = prr * qi + pri * qr;
            prr = nr;
        }
#pragma unroll
        for (int r = 0; r < 8; r++) {
            float lr = prr, li = pri;
#pragma unroll
            for (int w = 5; w < 8; w++) {
                int b = (r >> (7 - w)) & 1;
                float qr = b ? S[w] * S[w] : C[w] * C[w];
                float qi = -S[w] * C[w];
                float nr = lr * qr - li * qi;
                li = lr * qi + li * qr;
                lr = nr;
            }
            ar[r] = lr; ai[r] = li;
        }
    }

    // ---------------- 3) 4 entangling layers --------------------------
#pragma unroll
    for (int l = 0; l < NLAYERS; l++) {
#pragma unroll
        for (int i = 0; i < NQ; i++) {
            const float* u = &g_ucoef[(l * NQ + i) * 8];
            float u00r = __ldg(u + 0), u00i = __ldg(u + 1);
            float u01r = __ldg(u + 2), u01i = __ldg(u + 3);
            float u10r = __ldg(u + 4), u10i = __ldg(u + 5);
            float u11r = __ldg(u + 6), u11i = __ldg(u + 7);
            if (i < 5) {
                // gate on lane bit L = 4-i
                const int L = 4 - i;
                bool hi = (lane >> L) & 1;
                float dr  = hi ? u11r : u00r, di = hi ? u11i : u00i;
                float orr = hi ? u10r : u01r, oi = hi ? u10i : u01i;
#pragma unroll
                for (int r = 0; r < 8; r++) {
                    float pr = __shfl_xor_sync(0xffffffffu, ar[r], 1 << L);
                    float pi = __shfl_xor_sync(0xffffffffu, ai[r], 1 << L);
                    float mr = ar[r], mi = ai[r];
                    ar[r] = dr * mr - di * mi + orr * pr - oi * pi;
                    ai[r] = dr * mi + di * mr + orr * pi + oi * pr;
                }
            } else {
                // gate on local r-bit t = 7-i
                const int m = 1 << (7 - i);
#pragma unroll
                for (int r = 0; r < 8; r++) {
                    if (!(r & m)) {
                        int r1 = r | m;
                        float a_r = ar[r],  a_i = ai[r];
                        float b_r = ar[r1], b_i = ai[r1];
                        ar[r]  = u00r * a_r - u00i * a_i + u01r * b_r - u01i * b_i;
                        ai[r]  = u00r * a_i + u00i * a_r + u01r * b_i + u01i * b_r;
                        ar[r1] = u10r * a_r - u10i * a_i + u11r * b_r - u11i * b_i;
                        ai[r1] = u10r * a_i + u10i * a_r + u11r * b_i + u11i * b_r;
                    }
                }
            }
        }
        // CNOT chain (0,1)(1,2)(2,3)(3,4): control lane bit cl, target lane bit cl-1
#pragma unroll
        for (int cl = 4; cl >= 1; cl--) {
            bool ctrl = (lane >> cl) & 1;
            const int tmask = 1 << (cl - 1);
#pragma unroll
            for (int r = 0; r < 8; r++) {
                float pr = __shfl_xor_sync(0xffffffffu, ar[r], tmask);
                float pi = __shfl_xor_sync(0xffffffffu, ai[r], tmask);
                ar[r] = ctrl ? pr : ar[r];
                ai[r] = ctrl ? pi : ai[r];
            }
        }
        { // CNOT(4,5): control lane bit 0, target local bit 2 (swap r <-> r^4)
            bool ctrl = lane & 1;
#pragma unroll
            for (int r = 0; r < 4; r++) {
                float t0 = ar[r], t1 = ar[r + 4];
                ar[r] = ctrl ? t1 : t0; ar[r + 4] = ctrl ? t0 : t1;
                float s0 = ai[r], s1 = ai[r + 4];
                ai[r] = ctrl ? s1 : s0; ai[r + 4] = ctrl ? s0 : s1;
            }
        }
        { // CNOT(5,6): for r-bit2==1 flip bit1 -> swap (4,6),(5,7)  [register rename]
            float t;
            t = ar[4]; ar[4] = ar[6]; ar[6] = t;  t = ai[4]; ai[4] = ai[6]; ai[6] = t;
            t = ar[5]; ar[5] = ar[7]; ar[7] = t;  t = ai[5]; ai[5] = ai[7]; ai[7] = t;
        }
        { // CNOT(6,7): for r-bit1==1 flip bit0 -> swap (2,3),(6,7)  [register rename]
            float t;
            t = ar[2]; ar[2] = ar[3]; ar[3] = t;  t = ai[2]; ai[2] = ai[3]; ai[3] = t;
            t = ar[6]; ar[6] = ar[7]; ar[7] = t;  t = ai[6]; ai[6] = ai[7]; ai[7] = t;
        }
    }

    // ---------------- 4) expectation values <Z_i> ---------------------
    float p[8];
#pragma unroll
    for (int r = 0; r < 8; r++) p[r] = ar[r] * ar[r] + ai[r] * ai[r];
    float ptot = 0.f;
#pragma unroll
    for (int r = 0; r < 8; r++) ptot += p[r];

    float ev[NQ];
#pragma unroll
    for (int i = 0; i < 5; i++)
        ev[i] = ((lane >> (4 - i)) & 1) ? -ptot : ptot;
#pragma unroll
    for (int i = 5; i < 8; i++) {
        float s = 0.f;
#pragma unroll
        for (int r = 0; r < 8; r++)
            s += ((r >> (7 - i)) & 1) ? -p[r] : p[r];
        ev[i] = s;
    }
#pragma unroll
    for (int off = 16; off; off >>= 1)
#pragma unroll
        for (int i = 0; i < NQ; i++)
            ev[i] += __shfl_xor_sync(0xffffffffu, ev[i], off);

    // ---------------- 5) out[row] = ev @ Wout^T + bout ----------------
    const float4* bo4 = reinterpret_cast<const float4*>(bout);
    const float4* wo4 = reinterpret_cast<const float4*>(Wout);   // [DOUT][2] float4
    float4* out4 = reinterpret_cast<float4*>(out) + (size_t)row * (DOUT / 4);
#pragma unroll
    for (int j = 0; j < 8; j++) {
        int c4 = lane + 32 * j;       // float4 column index
        float4 o = __ldg(&bo4[c4]);
        int obase = c4 * 4;
        float* op = &o.x;
#pragma unroll
        for (int oo = 0; oo < 4; oo++) {
            float4 wa = __ldg(&wo4[(obase + oo) * 2 + 0]);
            float4 wb = __ldg(&wo4[(obase + oo) * 2 + 1]);
            op[oo] += ev[0] * wa.x + ev[1] * wa.y + ev[2] * wa.z + ev[3] * wa.w
                    + ev[4] * wb.x + ev[5] * wb.y + ev[6] * wb.z + ev[7] * wb.w;
        }
        out4[c4] = o;
    }
}

extern "C" void kernel_launch(void* const* d_in, const int* in_sizes, int n_in,
                              void* d_out, int out_size) {
    const float* x    = (const float*)d_in[0];
    const float* Win  = (const float*)d_in[1];
    const float* bin  = (const float*)d_in[2];
    const float* qw   = (const float*)d_in[3];
    const float* Wout = (const float*)d_in[4];
    const float* bout = (const float*)d_in[5];
    float* out = (float*)d_out;

    int B = in_sizes[0] / DIN;       // 8192
    prep_kernel<<<1, 32>>>(qw);
    qasa_kernel<<<B / 8, 256>>>(x, Win, bin, Wout, bout, out);
}